// round 2
// baseline (speedup 1.0000x reference)
#include <cuda_runtime.h>
#include <math.h>

// ---------------- constants ----------------
#define HDIM 256
#define NREL 480
#define NENT 23000
#define NTRI 8192
#define TSTEPS 10

// ---------------- device scratch (no runtime allocation allowed) ----------------
__device__ float g_tmp1[NREL * 512];
__device__ float g_mr[NREL * HDIM];
__device__ float g_attW[NREL * HDIM];
__device__ float g_baseR[NREL * NREL];
__device__ float g_t1[NREL * HDIM];
__device__ float g_ph[NREL * HDIM];
__device__ float g_gi2[NREL * 768];
__device__ float g_gh2[NREL * 768];
__device__ float g_h2rel[NREL * HDIM];
__device__ float g_P[(size_t)TSTEPS * NTRI * NREL];    // softmaxed attention
__device__ float g_X[(size_t)TSTEPS * NTRI * HDIM];    // attn @ mapped_rel
__device__ float g_GI[(size_t)TSTEPS * NTRI * 768];    // X @ Wih + bih
__device__ float g_GH[(size_t)NTRI * 768];
__device__ float g_H0[(size_t)NTRI * HDIM];
__device__ float g_H1[(size_t)NTRI * HDIM];
__device__ float g_prealign[(size_t)NENT * HDIM];
__device__ float g_U[(size_t)NTRI * HDIM];
__device__ double g_accum[3];  // [0]=match sq sum, [1]=softplus sum, [2]=pos sum

// ---------------- small helpers ----------------
__global__ void init_kernel(float* H, int n, double* accum) {
    int idx = blockIdx.x * blockDim.x + threadIdx.x;
    if (idx < n) H[idx] = 0.0f;
    if (idx < 3) accum[idx] = 0.0;
}

// C[m,n] = alpha * (sum_k A[m,k]*B[k,n] + bias[n]) + add[m,n]
__global__ void naive_gemm(const float* __restrict__ A, const float* __restrict__ B,
                           const float* __restrict__ bias, const float* __restrict__ add,
                           float* __restrict__ C, int M, int N, int K, float alpha) {
    int idx = blockIdx.x * blockDim.x + threadIdx.x;
    if (idx >= M * N) return;
    int m = idx / N, n = idx % N;
    float acc = 0.0f;
    const float* a = A + (size_t)m * K;
    for (int k = 0; k < K; k++) acc += a[k] * B[(size_t)k * N + n];
    if (bias) acc += bias[n];
    acc *= alpha;
    if (add) acc += add[idx];
    C[idx] = acc;
}

// C[m,n] = sum_k A[m,k]*B[n,k]
__global__ void naive_gemm_nt(const float* __restrict__ A, const float* __restrict__ B,
                              float* __restrict__ C, int M, int N, int K) {
    int idx = blockIdx.x * blockDim.x + threadIdx.x;
    if (idx >= M * N) return;
    int m = idx / N, n = idx % N;
    float acc = 0.0f;
    const float* a = A + (size_t)m * K;
    const float* b = B + (size_t)n * K;
    for (int k = 0; k < K; k++) acc += a[k] * b[k];
    C[idx] = acc;
}

// GRU gates: GI/GH already include their biases. Hnew = (1-z)*n + z*Hprev
__global__ void gru_gates(const float* __restrict__ GI, const float* __restrict__ GH,
                          const float* __restrict__ Hprev, float* __restrict__ Hnew, int M) {
    int idx = blockIdx.x * blockDim.x + threadIdx.x;
    if (idx >= M * HDIM) return;
    int m = idx >> 8;
    int c = idx & 255;
    const float* gi = GI + (size_t)m * 768;
    const float* gh = GH + (size_t)m * 768;
    float r = 1.0f / (1.0f + expf(-(gi[c] + gh[c])));
    float z = 1.0f / (1.0f + expf(-(gi[256 + c] + gh[256 + c])));
    float nn = tanhf(gi[512 + c] + r * gh[512 + c]);
    Hnew[idx] = (1.0f - z) * nn + z * Hprev[idx];
}

// masked softmax rows: P[t*NTRI+i, j] = softmax_j( where(cur*base==0, -1e9, cur*base) )
__global__ void softmax_p(const float* __restrict__ hist, const float* __restrict__ baseR,
                          const int* __restrict__ rel_idx, float* __restrict__ P) {
    int i = blockIdx.x;
    int t = blockIdx.y;
    int tid = threadIdx.x;  // 256 threads
    const float* cur = hist + (size_t)i * (TSTEPS * NREL) + (size_t)t * NREL;
    const float* br = baseR + (size_t)rel_idx[i] * NREL;
    __shared__ float v[NREL];
    __shared__ float red[256];
    float lmax = -3.0e38f;
    for (int j = tid; j < NREL; j += 256) {
        float a = cur[j] * br[j];
        float val = (a == 0.0f) ? -1.0e9f : a;
        v[j] = val;
        lmax = fmaxf(lmax, val);
    }
    red[tid] = lmax;
    __syncthreads();
    for (int o = 128; o > 0; o >>= 1) {
        if (tid < o) red[tid] = fmaxf(red[tid], red[tid + o]);
        __syncthreads();
    }
    float m = red[0];
    __syncthreads();
    float lsum = 0.0f;
    for (int j = tid; j < NREL; j += 256) {
        float e = expf(v[j] - m);
        v[j] = e;
        lsum += e;
    }
    red[tid] = lsum;
    __syncthreads();
    for (int o = 128; o > 0; o >>= 1) {
        if (tid < o) red[tid] += red[tid + o];
        __syncthreads();
    }
    float inv = 1.0f / red[0];
    float* prow = P + ((size_t)t * NTRI + i) * NREL;
    for (int j = tid; j < NREL; j += 256) prow[j] = v[j] * inv;
}

// ---------------- tiled SGEMM (NN, row-major A[M,K], B[K,N]) ----------------
#define BM 128
#define BN 128
#define BK 16
#define TM 8
#define TN 8

__global__ __launch_bounds__(256) void sgemm_nn(const float* __restrict__ A,
                                                const float* __restrict__ B,
                                                const float* __restrict__ bias,
                                                float* __restrict__ C,
                                                int M, int N, int K) {
    __shared__ float As[BK][BM];
    __shared__ float Bs[BK][BN];
    int tid = threadIdx.x;
    int m0 = blockIdx.y * BM;
    int n0 = blockIdx.x * BN;
    int tx = tid & 15;
    int ty = tid >> 4;
    float acc[TM][TN] = {};
    for (int k0 = 0; k0 < K; k0 += BK) {
#pragma unroll
        for (int l = 0; l < 2; l++) {
            int idx = tid + l * 256;
            int row = idx >> 2;
            int c4 = (idx & 3) << 2;
            float4 va = make_float4(0.f, 0.f, 0.f, 0.f);
            if (m0 + row < M) va = *(const float4*)&A[(size_t)(m0 + row) * K + k0 + c4];
            As[c4 + 0][row] = va.x;
            As[c4 + 1][row] = va.y;
            As[c4 + 2][row] = va.z;
            As[c4 + 3][row] = va.w;
        }
#pragma unroll
        for (int l = 0; l < 2; l++) {
            int idx = tid + l * 256;
            int row = idx >> 5;
            int c4 = (idx & 31) << 2;
            float4 vb = make_float4(0.f, 0.f, 0.f, 0.f);
            if (n0 + c4 < N) vb = *(const float4*)&B[(size_t)(k0 + row) * N + n0 + c4];
            *(float4*)&Bs[row][c4] = vb;
        }
        __syncthreads();
#pragma unroll
        for (int k = 0; k < BK; k++) {
            float ra[TM], rb[TN];
#pragma unroll
            for (int i = 0; i < TM; i++) ra[i] = As[k][ty * TM + i];
#pragma unroll
            for (int j = 0; j < TN; j++) rb[j] = Bs[k][tx * TN + j];
#pragma unroll
            for (int i = 0; i < TM; i++)
#pragma unroll
                for (int j = 0; j < TN; j++) acc[i][j] += ra[i] * rb[j];
        }
        __syncthreads();
    }
#pragma unroll
    for (int i = 0; i < TM; i++) {
        int m = m0 + ty * TM + i;
        if (m >= M) continue;
#pragma unroll
        for (int j = 0; j < TN; j++) {
            int n = n0 + tx * TN + j;
            if (n >= N) continue;
            float v = acc[i][j];
            if (bias) v += bias[n];
            C[(size_t)m * N + n] = v;
        }
    }
}

// ---------------- score GEMM (NT) with fused sigmoid/softplus/pos epilogue ----------------
__global__ __launch_bounds__(256) void sgemm_nt_score(const float* __restrict__ A,
                                                      const float* __restrict__ B,
                                                      const int* __restrict__ obj_idx,
                                                      float* __restrict__ out,
                                                      double* __restrict__ accum,
                                                      int M, int Nn, int K) {
    __shared__ float As[BK][BM];
    __shared__ float Bs[BK][BN];
    __shared__ double red[256];
    int tid = threadIdx.x;
    int m0 = blockIdx.y * BM;
    int n0 = blockIdx.x * BN;
    int tx = tid & 15;
    int ty = tid >> 4;
    float acc[TM][TN] = {};
    for (int k0 = 0; k0 < K; k0 += BK) {
#pragma unroll
        for (int l = 0; l < 2; l++) {
            int idx = tid + l * 256;
            int row = idx >> 2;
            int c4 = (idx & 3) << 2;
            float4 va = make_float4(0.f, 0.f, 0.f, 0.f);
            if (m0 + row < M) va = *(const float4*)&A[(size_t)(m0 + row) * K + k0 + c4];
            As[c4 + 0][row] = va.x;
            As[c4 + 1][row] = va.y;
            As[c4 + 2][row] = va.z;
            As[c4 + 3][row] = va.w;
        }
#pragma unroll
        for (int l = 0; l < 2; l++) {
            int idx = tid + l * 256;
            int n = idx >> 2;
            int k4 = (idx & 3) << 2;
            float4 vb = make_float4(0.f, 0.f, 0.f, 0.f);
            if (n0 + n < Nn) vb = *(const float4*)&B[(size_t)(n0 + n) * K + k0 + k4];
            Bs[k4 + 0][n] = vb.x;
            Bs[k4 + 1][n] = vb.y;
            Bs[k4 + 2][n] = vb.z;
            Bs[k4 + 3][n] = vb.w;
        }
        __syncthreads();
#pragma unroll
        for (int k = 0; k < BK; k++) {
            float ra[TM], rb[TN];
#pragma unroll
            for (int i = 0; i < TM; i++) ra[i] = As[k][ty * TM + i];
#pragma unroll
            for (int j = 0; j < TN; j++) rb[j] = Bs[k][tx * TN + j];
#pragma unroll
            for (int i = 0; i < TM; i++)
#pragma unroll
                for (int j = 0; j < TN; j++) acc[i][j] += ra[i] * rb[j];
        }
        __syncthreads();
    }
    double sp = 0.0, pos = 0.0;
#pragma unroll
    for (int i = 0; i < TM; i++) {
        int m = m0 + ty * TM + i;
        if (m >= M) continue;
        int obj = obj_idx[m];
#pragma unroll
        for (int j = 0; j < TN; j++) {
            int n = n0 + tx * TN + j;
            if (n >= Nn) continue;
            float s = acc[i][j];
            out[(size_t)m * Nn + n] = 1.0f / (1.0f + expf(-s));
            float spv;
            if (s > 20.0f) spv = s;
            else if (s < -20.0f) spv = expf(s);
            else spv = log1pf(expf(s));
            sp += (double)spv;
            if (n == obj) pos += (double)s;
        }
    }
    red[tid] = sp;
    __syncthreads();
    for (int o = 128; o > 0; o >>= 1) {
        if (tid < o) red[tid] += red[tid + o];
        __syncthreads();
    }
    if (tid == 0) atomicAdd(&accum[1], red[0]);
    __syncthreads();
    red[tid] = pos;
    __syncthreads();
    for (int o = 128; o > 0; o >>= 1) {
        if (tid < o) red[tid] += red[tid + o];
        __syncthreads();
    }
    if (tid == 0) atomicAdd(&accum[2], red[0]);
}

// ---------------- remaining elementwise / reduction kernels ----------------
__global__ void u_kernel(const float* __restrict__ prealign, const float* __restrict__ h2rel,
                         const int* __restrict__ sub_idx, const int* __restrict__ rel_idx,
                         float* __restrict__ U) {
    int idx = blockIdx.x * blockDim.x + threadIdx.x;
    if (idx >= NTRI * HDIM) return;
    int m = idx >> 8;
    int c = idx & 255;
    U[idx] = prealign[(size_t)sub_idx[m] * HDIM + c] * h2rel[(size_t)rel_idx[m] * HDIM + c];
}

__global__ void match_reduce(const float* __restrict__ ph_rel, const int* __restrict__ rel_idx,
                             const float* __restrict__ H, double* __restrict__ accum) {
    double local = 0.0;
    for (int idx = blockIdx.x * blockDim.x + threadIdx.x; idx < NTRI * HDIM;
         idx += gridDim.x * blockDim.x) {
        int m = idx >> 8;
        int c = idx & 255;
        float d = ph_rel[(size_t)rel_idx[m] * HDIM + c] - H[idx];
        local += (double)d * (double)d;
    }
    __shared__ double red[256];
    int tid = threadIdx.x;
    red[tid] = local;
    __syncthreads();
    for (int o = 128; o > 0; o >>= 1) {
        if (tid < o) red[tid] += red[tid + o];
        __syncthreads();
    }
    if (tid == 0) atomicAdd(&accum[0], red[0]);
}

__global__ void finalize_kernel(const double* __restrict__ accum, float* __restrict__ out) {
    out[0] = (float)(accum[0] / ((double)NTRI * (double)HDIM));
    out[1] = (float)((accum[1] - accum[2]) / ((double)NTRI * (double)NENT));
}

// ---------------- launch ----------------
extern "C" void kernel_launch(void* const* d_in, const int* in_sizes, int n_in,
                              void* d_out, int out_size) {
    const float* pre_emb = (const float*)d_in[0];
    const float* r_emb = (const float*)d_in[1];
    const float* hist = (const float*)d_in[2];
    const int* sub_idx = (const int*)d_in[3];
    const int* rel_idx = (const int*)d_in[4];
    const int* obj_idx = (const int*)d_in[5];
    int w = (n_in >= 23) ? 7 : 6;  // skip cur_ts scalar if present
    const float* Wm1 = (const float*)d_in[w + 0];
    const float* bm1 = (const float*)d_in[w + 1];
    const float* Wm2 = (const float*)d_in[w + 2];
    const float* bm2 = (const float*)d_in[w + 3];
    const float* Wattn = (const float*)d_in[w + 4];
    const float* battn = (const float*)d_in[w + 5];
    const float* Wh1 = (const float*)d_in[w + 6];
    const float* bh1 = (const float*)d_in[w + 7];
    const float* Wh2 = (const float*)d_in[w + 8];
    const float* bh2 = (const float*)d_in[w + 9];
    const float* Walign = (const float*)d_in[w + 10];
    const float* balign = (const float*)d_in[w + 11];
    const float* Wih = (const float*)d_in[w + 12];
    const float* Whh = (const float*)d_in[w + 13];
    const float* bih = (const float*)d_in[w + 14];
    const float* bhh = (const float*)d_in[w + 15];

    float *tmp1, *mr, *attW, *baseR, *t1, *ph, *gi2, *gh2, *h2rel;
    float *P, *X, *GI, *GH, *H0, *H1, *prealign, *U;
    double* accum;
    cudaGetSymbolAddress((void**)&tmp1, g_tmp1);
    cudaGetSymbolAddress((void**)&mr, g_mr);
    cudaGetSymbolAddress((void**)&attW, g_attW);
    cudaGetSymbolAddress((void**)&baseR, g_baseR);
    cudaGetSymbolAddress((void**)&t1, g_t1);
    cudaGetSymbolAddress((void**)&ph, g_ph);
    cudaGetSymbolAddress((void**)&gi2, g_gi2);
    cudaGetSymbolAddress((void**)&gh2, g_gh2);
    cudaGetSymbolAddress((void**)&h2rel, g_h2rel);
    cudaGetSymbolAddress((void**)&P, g_P);
    cudaGetSymbolAddress((void**)&X, g_X);
    cudaGetSymbolAddress((void**)&GI, g_GI);
    cudaGetSymbolAddress((void**)&GH, g_GH);
    cudaGetSymbolAddress((void**)&H0, g_H0);
    cudaGetSymbolAddress((void**)&H1, g_H1);
    cudaGetSymbolAddress((void**)&prealign, g_prealign);
    cudaGetSymbolAddress((void**)&U, g_U);
    cudaGetSymbolAddress((void**)&accum, g_accum);

    float* out = (float*)d_out;
    float* score = out + 2;

    // zero hidden state + accumulators
    init_kernel<<<(NTRI * HDIM + 255) / 256, 256>>>(H0, NTRI * HDIM, accum);

    // per-relation precompute
    naive_gemm<<<(NREL * 512 + 255) / 256, 256>>>(r_emb, Wm1, bm1, nullptr, tmp1, NREL, 512, HDIM, 1.0f);
    naive_gemm<<<(NREL * HDIM + 255) / 256, 256>>>(tmp1, Wm2, bm2, nullptr, mr, NREL, HDIM, 512, 1.0f);
    naive_gemm<<<(NREL * HDIM + 255) / 256, 256>>>(mr, Wattn, battn, nullptr, attW, NREL, HDIM, HDIM, 1.0f);
    naive_gemm_nt<<<(NREL * NREL + 255) / 256, 256>>>(attW, mr, baseR, NREL, NREL, HDIM);
    naive_gemm<<<(NREL * HDIM + 255) / 256, 256>>>(mr, Wh1, bh1, nullptr, t1, NREL, HDIM, HDIM, 1.0f);
    naive_gemm<<<(NREL * HDIM + 255) / 256, 256>>>(t1, Wh2, bh2, mr, ph, NREL, HDIM, HDIM, 0.1f);
    naive_gemm<<<(NREL * 768 + 255) / 256, 256>>>(mr, Wih, bih, nullptr, gi2, NREL, 768, HDIM, 1.0f);
    naive_gemm<<<(NREL * 768 + 255) / 256, 256>>>(ph, Whh, bhh, nullptr, gh2, NREL, 768, HDIM, 1.0f);
    gru_gates<<<(NREL * HDIM + 255) / 256, 256>>>(gi2, gh2, ph, h2rel, NREL);

    // attention softmax for all (i, t)
    softmax_p<<<dim3(NTRI, TSTEPS), 256>>>(hist, baseR, rel_idx, P);

    // X = P @ mr   [T*N, 256], K=480
    sgemm_nn<<<dim3(HDIM / BN, (TSTEPS * NTRI) / BM), 256>>>(P, mr, nullptr, X,
                                                             TSTEPS * NTRI, HDIM, NREL);
    // GI = X @ Wih + bih   [T*N, 768], K=256
    sgemm_nn<<<dim3(768 / BN, (TSTEPS * NTRI) / BM), 256>>>(X, Wih, bih, GI,
                                                            TSTEPS * NTRI, 768, HDIM);
    // sequential GRU scan
    float* Hc = H0;
    float* Hn = H1;
    for (int t = 0; t < TSTEPS; t++) {
        sgemm_nn<<<dim3(768 / BN, NTRI / BM), 256>>>(Hc, Whh, bhh, GH, NTRI, 768, HDIM);
        gru_gates<<<(NTRI * HDIM + 255) / 256, 256>>>(GI + (size_t)t * NTRI * 768, GH, Hc, Hn, NTRI);
        float* tmp = Hc; Hc = Hn; Hn = tmp;
    }

    // match loss
    match_reduce<<<2048, 256>>>(ph, rel_idx, Hc, accum);

    // entity alignment + u = aligned_sub * h2
    sgemm_nn<<<dim3(HDIM / BN, (NENT + BM - 1) / BM), 256>>>(pre_emb, Walign, balign, prealign,
                                                             NENT, HDIM, HDIM);
    u_kernel<<<(NTRI * HDIM + 255) / 256, 256>>>(prealign, h2rel, sub_idx, rel_idx, U);

    // score = sigmoid(U @ prealign^T) + fused loss reductions
    sgemm_nt_score<<<dim3((NENT + BN - 1) / BN, NTRI / BM), 256>>>(U, prealign, obj_idx, score,
                                                                   accum, NTRI, NENT, HDIM);

    finalize_kernel<<<1, 1>>>(accum, out);
}

// round 3
// speedup vs baseline: 2.1276x; 2.1276x over previous
#include <cuda_runtime.h>
#include <math.h>
#include <stdint.h>

// ---------------- constants ----------------
#define HDIM 256
#define NREL 480
#define NENT 23000
#define NTRI 8192
#define TSTEPS 10

// ---------------- device scratch ----------------
__device__ float g_tmp1[NREL * 512];
__device__ float g_mr[NREL * HDIM];
__device__ float g_attW[NREL * HDIM];
__device__ float g_baseR[NREL * NREL];
__device__ float g_t1[NREL * HDIM];
__device__ float g_ph[NREL * HDIM];
__device__ float g_gi2[NREL * 768];
__device__ float g_gh2[NREL * 768];
__device__ float g_h2rel[NREL * HDIM];
__device__ float g_P[(size_t)TSTEPS * NTRI * NREL];
__device__ float g_X[(size_t)TSTEPS * NTRI * HDIM];
__device__ float g_GI[(size_t)TSTEPS * NTRI * 768];
__device__ float g_GH[(size_t)NTRI * 768];
__device__ float g_H0[(size_t)NTRI * HDIM];
__device__ float g_H1[(size_t)NTRI * HDIM];
__device__ float g_prealign[(size_t)NENT * HDIM];
__device__ float g_U[(size_t)NTRI * HDIM];
__device__ double g_accum[3];

// ---------------- tf32 mma helpers ----------------
__device__ __forceinline__ uint32_t f2tf32(float f) {
    uint32_t u;
    asm("cvt.rna.tf32.f32 %0, %1;" : "=r"(u) : "f"(f));
    return u;
}

__device__ __forceinline__ void mma_tf32(float* d, const uint32_t* a, const uint32_t* b) {
    asm volatile(
        "mma.sync.aligned.m16n8k8.row.col.f32.tf32.tf32.f32 "
        "{%0,%1,%2,%3}, {%4,%5,%6,%7}, {%8,%9}, {%0,%1,%2,%3};"
        : "+f"(d[0]), "+f"(d[1]), "+f"(d[2]), "+f"(d[3])
        : "r"(a[0]), "r"(a[1]), "r"(a[2]), "r"(a[3]), "r"(b[0]), "r"(b[1]));
}

#define ASTRIDE 20
#define BSTRIDE 136

// ---------------- mma GEMM NN: C[M,N] = alpha*(A@B + bias) + add ----------------
// block 256 thr, tile 128x128, BK=16. Requires K%16==0, N%128==0. M arbitrary.
__global__ __launch_bounds__(256) void mma_gemm_nn(const float* __restrict__ A,
                                                   const float* __restrict__ B,
                                                   const float* __restrict__ bias,
                                                   const float* __restrict__ add,
                                                   float* __restrict__ C,
                                                   int M, int N, int K, float alpha) {
    __shared__ uint32_t As[128 * ASTRIDE];
    __shared__ uint32_t Bs[16 * BSTRIDE];
    int tid = threadIdx.x;
    int m0 = blockIdx.y * 128;
    int n0 = blockIdx.x * 128;
    int lane = tid & 31;
    int wid = tid >> 5;
    int warp_m = wid >> 2;   // 0..1 -> 64 rows each
    int warp_n = wid & 3;    // 0..3 -> 32 cols each
    int g = lane >> 2;       // group id 0..7
    int tg = lane & 3;       // thread in group

    float acc[4][4][4];
#pragma unroll
    for (int i = 0; i < 4; i++)
#pragma unroll
        for (int j = 0; j < 4; j++)
#pragma unroll
            for (int r = 0; r < 4; r++) acc[i][j][r] = 0.0f;

    for (int k0 = 0; k0 < K; k0 += 16) {
        // load A tile [128 x 16]
#pragma unroll
        for (int l = 0; l < 2; l++) {
            int idx = tid + l * 256;
            int row = idx >> 2;
            int c4 = (idx & 3) << 2;
            float4 v = make_float4(0.f, 0.f, 0.f, 0.f);
            if (m0 + row < M) v = *(const float4*)&A[(size_t)(m0 + row) * K + k0 + c4];
            uint32_t* dst = &As[row * ASTRIDE + c4];
            dst[0] = f2tf32(v.x);
            dst[1] = f2tf32(v.y);
            dst[2] = f2tf32(v.z);
            dst[3] = f2tf32(v.w);
        }
        // load B tile [16 x 128]
#pragma unroll
        for (int l = 0; l < 2; l++) {
            int idx = tid + l * 256;
            int row = idx >> 5;
            int c4 = (idx & 31) << 2;
            float4 v = *(const float4*)&B[(size_t)(k0 + row) * N + n0 + c4];
            uint32_t* dst = &Bs[row * BSTRIDE + c4];
            dst[0] = f2tf32(v.x);
            dst[1] = f2tf32(v.y);
            dst[2] = f2tf32(v.z);
            dst[3] = f2tf32(v.w);
        }
        __syncthreads();
#pragma unroll
        for (int kk = 0; kk < 16; kk += 8) {
            uint32_t af[4][4], bf[4][2];
#pragma unroll
            for (int mi = 0; mi < 4; mi++) {
                int rb = warp_m * 64 + mi * 16 + g;
                af[mi][0] = As[rb * ASTRIDE + kk + tg];
                af[mi][1] = As[(rb + 8) * ASTRIDE + kk + tg];
                af[mi][2] = As[rb * ASTRIDE + kk + tg + 4];
                af[mi][3] = As[(rb + 8) * ASTRIDE + kk + tg + 4];
            }
#pragma unroll
            for (int ni = 0; ni < 4; ni++) {
                int nb = warp_n * 32 + ni * 8 + g;
                bf[ni][0] = Bs[(kk + tg) * BSTRIDE + nb];
                bf[ni][1] = Bs[(kk + tg + 4) * BSTRIDE + nb];
            }
#pragma unroll
            for (int mi = 0; mi < 4; mi++)
#pragma unroll
                for (int ni = 0; ni < 4; ni++) mma_tf32(acc[mi][ni], af[mi], bf[ni]);
        }
        __syncthreads();
    }
    // epilogue
#pragma unroll
    for (int mi = 0; mi < 4; mi++) {
#pragma unroll
        for (int r = 0; r < 4; r++) {
            int m = m0 + warp_m * 64 + mi * 16 + g + ((r >> 1) << 3);
            if (m >= M) continue;
#pragma unroll
            for (int ni = 0; ni < 4; ni++) {
                int n = n0 + warp_n * 32 + ni * 8 + tg * 2 + (r & 1);
                float v = acc[mi][ni][r];
                if (bias) v += bias[n];
                v *= alpha;
                size_t off = (size_t)m * N + n;
                if (add) v += add[off];
                C[off] = v;
            }
        }
    }
}

// ---------------- mma GEMM NT + score epilogue ----------------
// score = sigmoid(A[M,K] @ B[Nn,K]^T); accumulate softplus sum & pos sum.
// M%128==0, K%16==0, Nn arbitrary.
__global__ __launch_bounds__(256) void mma_gemm_nt_score(const float* __restrict__ A,
                                                         const float* __restrict__ B,
                                                         const int* __restrict__ obj_idx,
                                                         float* __restrict__ out,
                                                         double* __restrict__ accum,
                                                         int M, int Nn, int K) {
    __shared__ uint32_t As[128 * ASTRIDE];
    __shared__ uint32_t Bs[16 * BSTRIDE];
    __shared__ double red[256];
    int tid = threadIdx.x;
    int m0 = blockIdx.y * 128;
    int n0 = blockIdx.x * 128;
    int lane = tid & 31;
    int wid = tid >> 5;
    int warp_m = wid >> 2;
    int warp_n = wid & 3;
    int g = lane >> 2;
    int tg = lane & 3;

    float acc[4][4][4];
#pragma unroll
    for (int i = 0; i < 4; i++)
#pragma unroll
        for (int j = 0; j < 4; j++)
#pragma unroll
            for (int r = 0; r < 4; r++) acc[i][j][r] = 0.0f;

    for (int k0 = 0; k0 < K; k0 += 16) {
#pragma unroll
        for (int l = 0; l < 2; l++) {
            int idx = tid + l * 256;
            int row = idx >> 2;
            int c4 = (idx & 3) << 2;
            float4 v = *(const float4*)&A[(size_t)(m0 + row) * K + k0 + c4];
            uint32_t* dst = &As[row * ASTRIDE + c4];
            dst[0] = f2tf32(v.x);
            dst[1] = f2tf32(v.y);
            dst[2] = f2tf32(v.z);
            dst[3] = f2tf32(v.w);
        }
        // B tile: rows are entities (n), cols are k -> store transposed into Bs[k][n]
#pragma unroll
        for (int l = 0; l < 2; l++) {
            int idx = tid + l * 256;
            int n = idx >> 2;
            int k4 = (idx & 3) << 2;
            float4 v = make_float4(0.f, 0.f, 0.f, 0.f);
            if (n0 + n < Nn) v = *(const float4*)&B[(size_t)(n0 + n) * K + k0 + k4];
            Bs[(k4 + 0) * BSTRIDE + n] = f2tf32(v.x);
            Bs[(k4 + 1) * BSTRIDE + n] = f2tf32(v.y);
            Bs[(k4 + 2) * BSTRIDE + n] = f2tf32(v.z);
            Bs[(k4 + 3) * BSTRIDE + n] = f2tf32(v.w);
        }
        __syncthreads();
#pragma unroll
        for (int kk = 0; kk < 16; kk += 8) {
            uint32_t af[4][4], bf[4][2];
#pragma unroll
            for (int mi = 0; mi < 4; mi++) {
                int rb = warp_m * 64 + mi * 16 + g;
                af[mi][0] = As[rb * ASTRIDE + kk + tg];
                af[mi][1] = As[(rb + 8) * ASTRIDE + kk + tg];
                af[mi][2] = As[rb * ASTRIDE + kk + tg + 4];
                af[mi][3] = As[(rb + 8) * ASTRIDE + kk + tg + 4];
            }
#pragma unroll
            for (int ni = 0; ni < 4; ni++) {
                int nb = warp_n * 32 + ni * 8 + g;
                bf[ni][0] = Bs[(kk + tg) * BSTRIDE + nb];
                bf[ni][1] = Bs[(kk + tg + 4) * BSTRIDE + nb];
            }
#pragma unroll
            for (int mi = 0; mi < 4; mi++)
#pragma unroll
                for (int ni = 0; ni < 4; ni++) mma_tf32(acc[mi][ni], af[mi], bf[ni]);
        }
        __syncthreads();
    }

    double sp = 0.0, pos = 0.0;
#pragma unroll
    for (int mi = 0; mi < 4; mi++) {
#pragma unroll
        for (int r = 0; r < 4; r++) {
            int m = m0 + warp_m * 64 + mi * 16 + g + ((r >> 1) << 3);
            int obj = obj_idx[m];
#pragma unroll
            for (int ni = 0; ni < 4; ni++) {
                int n = n0 + warp_n * 32 + ni * 8 + tg * 2 + (r & 1);
                if (n >= Nn) continue;
                float s = acc[mi][ni][r];
                out[(size_t)m * Nn + n] = 1.0f / (1.0f + __expf(-s));
                float spv;
                if (s > 20.0f) spv = s;
                else if (s < -20.0f) spv = __expf(s);
                else spv = log1pf(__expf(s));
                sp += (double)spv;
                if (n == obj) pos += (double)s;
            }
        }
    }
    red[tid] = sp;
    __syncthreads();
    for (int o = 128; o > 0; o >>= 1) {
        if (tid < o) red[tid] += red[tid + o];
        __syncthreads();
    }
    if (tid == 0) atomicAdd(&accum[1], red[0]);
    __syncthreads();
    red[tid] = pos;
    __syncthreads();
    for (int o = 128; o > 0; o >>= 1) {
        if (tid < o) red[tid] += red[tid + o];
        __syncthreads();
    }
    if (tid == 0) atomicAdd(&accum[2], red[0]);
}

// ---------------- small helpers ----------------
__global__ void init_kernel(float* H, int n, double* accum) {
    int idx = blockIdx.x * blockDim.x + threadIdx.x;
    if (idx < n) H[idx] = 0.0f;
    if (idx < 3) accum[idx] = 0.0;
}

// C[m,n] = sum_k A[m,k]*B[n,k]   (tiny, 480x480x256)
__global__ void naive_gemm_nt(const float* __restrict__ A, const float* __restrict__ B,
                              float* __restrict__ C, int M, int N, int K) {
    int idx = blockIdx.x * blockDim.x + threadIdx.x;
    if (idx >= M * N) return;
    int m = idx / N, n = idx % N;
    float acc = 0.0f;
    const float* a = A + (size_t)m * K;
    const float* b = B + (size_t)n * K;
    for (int k = 0; k < K; k++) acc += a[k] * b[k];
    C[idx] = acc;
}

__global__ void gru_gates(const float* __restrict__ GI, const float* __restrict__ GH,
                          const float* __restrict__ Hprev, float* __restrict__ Hnew, int M) {
    int idx = blockIdx.x * blockDim.x + threadIdx.x;
    if (idx >= M * HDIM) return;
    int m = idx >> 8;
    int c = idx & 255;
    const float* gi = GI + (size_t)m * 768;
    const float* gh = GH + (size_t)m * 768;
    float r = 1.0f / (1.0f + expf(-(gi[c] + gh[c])));
    float z = 1.0f / (1.0f + expf(-(gi[256 + c] + gh[256 + c])));
    float nn = tanhf(gi[512 + c] + r * gh[512 + c]);
    Hnew[idx] = (1.0f - z) * nn + z * Hprev[idx];
}

__global__ void softmax_p(const float* __restrict__ hist, const float* __restrict__ baseR,
                          const int* __restrict__ rel_idx, float* __restrict__ P) {
    int i = blockIdx.x;
    int t = blockIdx.y;
    int tid = threadIdx.x;
    const float* cur = hist + (size_t)i * (TSTEPS * NREL) + (size_t)t * NREL;
    const float* br = baseR + (size_t)rel_idx[i] * NREL;
    __shared__ float v[NREL];
    __shared__ float red[256];
    float lmax = -3.0e38f;
    for (int j = tid; j < NREL; j += 256) {
        float a = cur[j] * br[j];
        float val = (a == 0.0f) ? -1.0e9f : a;
        v[j] = val;
        lmax = fmaxf(lmax, val);
    }
    red[tid] = lmax;
    __syncthreads();
    for (int o = 128; o > 0; o >>= 1) {
        if (tid < o) red[tid] = fmaxf(red[tid], red[tid + o]);
        __syncthreads();
    }
    float m = red[0];
    __syncthreads();
    float lsum = 0.0f;
    for (int j = tid; j < NREL; j += 256) {
        float e = expf(v[j] - m);
        v[j] = e;
        lsum += e;
    }
    red[tid] = lsum;
    __syncthreads();
    for (int o = 128; o > 0; o >>= 1) {
        if (tid < o) red[tid] += red[tid + o];
        __syncthreads();
    }
    float inv = 1.0f / red[0];
    float* prow = P + ((size_t)t * NTRI + i) * NREL;
    for (int j = tid; j < NREL; j += 256) prow[j] = v[j] * inv;
}

__global__ void u_kernel(const float* __restrict__ prealign, const float* __restrict__ h2rel,
                         const int* __restrict__ sub_idx, const int* __restrict__ rel_idx,
                         float* __restrict__ U) {
    int idx = blockIdx.x * blockDim.x + threadIdx.x;
    if (idx >= NTRI * HDIM) return;
    int m = idx >> 8;
    int c = idx & 255;
    U[idx] = prealign[(size_t)sub_idx[m] * HDIM + c] * h2rel[(size_t)rel_idx[m] * HDIM + c];
}

__global__ void match_reduce(const float* __restrict__ ph_rel, const int* __restrict__ rel_idx,
                             const float* __restrict__ H, double* __restrict__ accum) {
    double local = 0.0;
    for (int idx = blockIdx.x * blockDim.x + threadIdx.x; idx < NTRI * HDIM;
         idx += gridDim.x * blockDim.x) {
        int m = idx >> 8;
        int c = idx & 255;
        float d = ph_rel[(size_t)rel_idx[m] * HDIM + c] - H[idx];
        local += (double)d * (double)d;
    }
    __shared__ double red[256];
    int tid = threadIdx.x;
    red[tid] = local;
    __syncthreads();
    for (int o = 128; o > 0; o >>= 1) {
        if (tid < o) red[tid] += red[tid + o];
        __syncthreads();
    }
    if (tid == 0) atomicAdd(&accum[0], red[0]);
}

__global__ void finalize_kernel(const double* __restrict__ accum, float* __restrict__ out) {
    out[0] = (float)(accum[0] / ((double)NTRI * (double)HDIM));
    out[1] = (float)((accum[1] - accum[2]) / ((double)NTRI * (double)NENT));
}

// ---------------- launch ----------------
extern "C" void kernel_launch(void* const* d_in, const int* in_sizes, int n_in,
                              void* d_out, int out_size) {
    const float* pre_emb = (const float*)d_in[0];
    const float* r_emb = (const float*)d_in[1];
    const float* hist = (const float*)d_in[2];
    const int* sub_idx = (const int*)d_in[3];
    const int* rel_idx = (const int*)d_in[4];
    const int* obj_idx = (const int*)d_in[5];
    int w = (n_in >= 23) ? 7 : 6;
    const float* Wm1 = (const float*)d_in[w + 0];
    const float* bm1 = (const float*)d_in[w + 1];
    const float* Wm2 = (const float*)d_in[w + 2];
    const float* bm2 = (const float*)d_in[w + 3];
    const float* Wattn = (const float*)d_in[w + 4];
    const float* battn = (const float*)d_in[w + 5];
    const float* Wh1 = (const float*)d_in[w + 6];
    const float* bh1 = (const float*)d_in[w + 7];
    const float* Wh2 = (const float*)d_in[w + 8];
    const float* bh2 = (const float*)d_in[w + 9];
    const float* Walign = (const float*)d_in[w + 10];
    const float* balign = (const float*)d_in[w + 11];
    const float* Wih = (const float*)d_in[w + 12];
    const float* Whh = (const float*)d_in[w + 13];
    const float* bih = (const float*)d_in[w + 14];
    const float* bhh = (const float*)d_in[w + 15];

    float *tmp1, *mr, *attW, *baseR, *t1, *ph, *gi2, *gh2, *h2rel;
    float *P, *X, *GI, *GH, *H0, *H1, *prealign, *U;
    double* accum;
    cudaGetSymbolAddress((void**)&tmp1, g_tmp1);
    cudaGetSymbolAddress((void**)&mr, g_mr);
    cudaGetSymbolAddress((void**)&attW, g_attW);
    cudaGetSymbolAddress((void**)&baseR, g_baseR);
    cudaGetSymbolAddress((void**)&t1, g_t1);
    cudaGetSymbolAddress((void**)&ph, g_ph);
    cudaGetSymbolAddress((void**)&gi2, g_gi2);
    cudaGetSymbolAddress((void**)&gh2, g_gh2);
    cudaGetSymbolAddress((void**)&h2rel, g_h2rel);
    cudaGetSymbolAddress((void**)&P, g_P);
    cudaGetSymbolAddress((void**)&X, g_X);
    cudaGetSymbolAddress((void**)&GI, g_GI);
    cudaGetSymbolAddress((void**)&GH, g_GH);
    cudaGetSymbolAddress((void**)&H0, g_H0);
    cudaGetSymbolAddress((void**)&H1, g_H1);
    cudaGetSymbolAddress((void**)&prealign, g_prealign);
    cudaGetSymbolAddress((void**)&U, g_U);
    cudaGetSymbolAddress((void**)&accum, g_accum);

    float* out = (float*)d_out;
    float* score = out + 2;

    init_kernel<<<(NTRI * HDIM + 255) / 256, 256>>>(H0, NTRI * HDIM, accum);

    // per-relation precompute (tf32 mma; tiny M=480)
    mma_gemm_nn<<<dim3(4, 4), 256>>>(r_emb, Wm1, bm1, nullptr, tmp1, NREL, 512, HDIM, 1.0f);
    mma_gemm_nn<<<dim3(2, 4), 256>>>(tmp1, Wm2, bm2, nullptr, mr, NREL, HDIM, 512, 1.0f);
    mma_gemm_nn<<<dim3(2, 4), 256>>>(mr, Wattn, battn, nullptr, attW, NREL, HDIM, HDIM, 1.0f);
    naive_gemm_nt<<<(NREL * NREL + 255) / 256, 256>>>(attW, mr, baseR, NREL, NREL, HDIM);
    mma_gemm_nn<<<dim3(2, 4), 256>>>(mr, Wh1, bh1, nullptr, t1, NREL, HDIM, HDIM, 1.0f);
    mma_gemm_nn<<<dim3(2, 4), 256>>>(t1, Wh2, bh2, mr, ph, NREL, HDIM, HDIM, 0.1f);
    mma_gemm_nn<<<dim3(6, 4), 256>>>(mr, Wih, bih, nullptr, gi2, NREL, 768, HDIM, 1.0f);
    mma_gemm_nn<<<dim3(6, 4), 256>>>(ph, Whh, bhh, nullptr, gh2, NREL, 768, HDIM, 1.0f);
    gru_gates<<<(NREL * HDIM + 255) / 256, 256>>>(gi2, gh2, ph, h2rel, NREL);

    // attention softmax
    softmax_p<<<dim3(NTRI, TSTEPS), 256>>>(hist, baseR, rel_idx, P);

    // X = P @ mr  [81920, 256], K=480
    mma_gemm_nn<<<dim3(2, (TSTEPS * NTRI) / 128), 256>>>(P, mr, nullptr, nullptr, X,
                                                         TSTEPS * NTRI, HDIM, NREL, 1.0f);
    // GI = X @ Wih + bih  [81920, 768], K=256
    mma_gemm_nn<<<dim3(6, (TSTEPS * NTRI) / 128), 256>>>(X, Wih, bih, nullptr, GI,
                                                         TSTEPS * NTRI, 768, HDIM, 1.0f);
    // sequential GRU scan
    float* Hc = H0;
    float* Hn = H1;
    for (int t = 0; t < TSTEPS; t++) {
        mma_gemm_nn<<<dim3(6, NTRI / 128), 256>>>(Hc, Whh, bhh, nullptr, GH, NTRI, 768, HDIM, 1.0f);
        gru_gates<<<(NTRI * HDIM + 255) / 256, 256>>>(GI + (size_t)t * NTRI * 768, GH, Hc, Hn, NTRI);
        float* tmp = Hc; Hc = Hn; Hn = tmp;
    }

    match_reduce<<<2048, 256>>>(ph, rel_idx, Hc, accum);

    // prealign = pre_emb @ Walign + balign  [23000, 256]
    mma_gemm_nn<<<dim3(2, (NENT + 127) / 128), 256>>>(pre_emb, Walign, balign, nullptr,
                                                      prealign, NENT, HDIM, HDIM, 1.0f);
    u_kernel<<<(NTRI * HDIM + 255) / 256, 256>>>(prealign, h2rel, sub_idx, rel_idx, U);

    // score = sigmoid(U @ prealign^T) + fused loss reductions
    mma_gemm_nt_score<<<dim3((NENT + 127) / 128, NTRI / 128), 256>>>(U, prealign, obj_idx,
                                                                     score, accum, NTRI, NENT, HDIM);

    finalize_kernel<<<1, 1>>>(accum, out);
}

// round 4
// speedup vs baseline: 2.5735x; 1.2096x over previous
#include <cuda_runtime.h>
#include <math.h>
#include <stdint.h>

// ---------------- constants ----------------
#define HDIM 256
#define NREL 480
#define NENT 23000
#define NTRI 8192
#define TSTEPS 10

// ---------------- device scratch ----------------
__device__ float g_tmp1[NREL * 512];
__device__ float g_mr[NREL * HDIM];
__device__ float g_attW[NREL * HDIM];
__device__ float g_baseR[NREL * NREL];
__device__ float g_t1[NREL * HDIM];
__device__ float g_ph[NREL * HDIM];
__device__ float g_gi2[NREL * 768];
__device__ float g_gh2[NREL * 768];
__device__ float g_h2rel[NREL * HDIM];
__device__ float g_P[(size_t)TSTEPS * NTRI * NREL];
__device__ float g_GI[(size_t)TSTEPS * NTRI * 768];
__device__ float g_GH[(size_t)NTRI * 768];
__device__ float g_H0[(size_t)NTRI * HDIM];
__device__ float g_H1[(size_t)NTRI * HDIM];
__device__ float g_prealign[(size_t)NENT * HDIM];
__device__ float g_U[(size_t)NTRI * HDIM];
__device__ double g_accum[3];

// ---------------- helpers ----------------
__device__ __forceinline__ uint32_t f2tf32(float f) {
    uint32_t u;
    asm("cvt.rna.tf32.f32 %0, %1;" : "=r"(u) : "f"(f));
    return u;
}

__device__ __forceinline__ void mma_tf32(float* d, const uint32_t* a, const uint32_t* b) {
    asm volatile(
        "mma.sync.aligned.m16n8k8.row.col.f32.tf32.tf32.f32 "
        "{%0,%1,%2,%3}, {%4,%5,%6,%7}, {%8,%9}, {%0,%1,%2,%3};"
        : "+f"(d[0]), "+f"(d[1]), "+f"(d[2]), "+f"(d[3])
        : "r"(a[0]), "r"(a[1]), "r"(a[2]), "r"(a[3]), "r"(b[0]), "r"(b[1]));
}

__device__ __forceinline__ void cp_async16(uint32_t dst, const void* src) {
    asm volatile("cp.async.cg.shared.global [%0], [%1], 16;" ::"r"(dst), "l"(src));
}
__device__ __forceinline__ void cp_commit() { asm volatile("cp.async.commit_group;"); }
template <int N>
__device__ __forceinline__ void cp_wait() {
    asm volatile("cp.async.wait_group %0;" ::"n"(N));
}

#define ASTR 20    // floats per A-tile row (16 + 4 pad): conflict-free
#define BSTR 136   // floats per B-tile row (128 + 8 pad): conflict-free

// ---------------- pipelined mma GEMM NN: C = alpha*(A@B + bias) + add ----------------
// tile 128x128, BK=16, 2-stage cp.async. Requires N%128==0, K%16==0. M arbitrary.
__global__ __launch_bounds__(256) void mma_nn(const float* __restrict__ A,
                                              const float* __restrict__ B,
                                              const float* __restrict__ bias,
                                              const float* __restrict__ add,
                                              float* __restrict__ C,
                                              int M, int N, int K, float alpha) {
    __shared__ float As[2][128 * ASTR];
    __shared__ float Bs[2][16 * BSTR];
    int tid = threadIdx.x;
    int m0 = blockIdx.y * 128;
    int n0 = blockIdx.x * 128;
    int lane = tid & 31;
    int wid = tid >> 5;
    int warp_m = wid >> 2;
    int warp_n = wid & 3;
    int g = lane >> 2;
    int tg = lane & 3;

    // load geometry
    int arow = tid >> 2;            // 0..63 (and +64)
    int ac4 = (tid & 3) << 2;
    int am0 = min(m0 + arow, M - 1);
    int am1 = min(m0 + arow + 64, M - 1);
    const float* asrc0 = A + (size_t)am0 * K + ac4;
    const float* asrc1 = A + (size_t)am1 * K + ac4;
    int brow = tid >> 5;            // 0..7 (and +8)
    int bc4 = (tid & 31) << 2;
    const float* bsrc0 = B + (size_t)brow * N + n0 + bc4;
    const float* bsrc1 = B + (size_t)(brow + 8) * N + n0 + bc4;

    uint32_t as_b = (uint32_t)__cvta_generic_to_shared(&As[0][0]);
    uint32_t bs_b = (uint32_t)__cvta_generic_to_shared(&Bs[0][0]);
    uint32_t ad0 = as_b + (arow * ASTR + ac4) * 4;
    uint32_t ad1 = as_b + ((arow + 64) * ASTR + ac4) * 4;
    uint32_t bd0 = bs_b + (brow * BSTR + bc4) * 4;
    uint32_t bd1 = bs_b + ((brow + 8) * BSTR + bc4) * 4;
    const uint32_t abuf = 128 * ASTR * 4;
    const uint32_t bbuf = 16 * BSTR * 4;

    float acc[4][4][4];
#pragma unroll
    for (int i = 0; i < 4; i++)
#pragma unroll
        for (int j = 0; j < 4; j++)
#pragma unroll
            for (int r = 0; r < 4; r++) acc[i][j][r] = 0.0f;

    int KT = K >> 4;
    // prologue: stage tile 0 into buf 0
    cp_async16(ad0, asrc0);
    cp_async16(ad1, asrc1);
    cp_async16(bd0, bsrc0);
    cp_async16(bd1, bsrc1);
    cp_commit();

    for (int kt = 0; kt < KT; kt++) {
        int buf = kt & 1;
        if (kt + 1 < KT) {
            int nb = (kt + 1) & 1;
            int koff = (kt + 1) << 4;
            cp_async16(ad0 + nb * abuf, asrc0 + koff);
            cp_async16(ad1 + nb * abuf, asrc1 + koff);
            cp_async16(bd0 + nb * bbuf, bsrc0 + (size_t)koff * N);
            cp_async16(bd1 + nb * bbuf, bsrc1 + (size_t)koff * N);
        }
        cp_commit();
        cp_wait<1>();
        __syncthreads();
        const float* as = As[buf];
        const float* bs = Bs[buf];
#pragma unroll
        for (int kk = 0; kk < 16; kk += 8) {
            uint32_t af[4][4], bf[4][2];
#pragma unroll
            for (int mi = 0; mi < 4; mi++) {
                int rb = warp_m * 64 + mi * 16 + g;
                af[mi][0] = f2tf32(as[rb * ASTR + kk + tg]);
                af[mi][1] = f2tf32(as[(rb + 8) * ASTR + kk + tg]);
                af[mi][2] = f2tf32(as[rb * ASTR + kk + tg + 4]);
                af[mi][3] = f2tf32(as[(rb + 8) * ASTR + kk + tg + 4]);
            }
#pragma unroll
            for (int ni = 0; ni < 4; ni++) {
                int nb = warp_n * 32 + ni * 8 + g;
                bf[ni][0] = f2tf32(bs[(kk + tg) * BSTR + nb]);
                bf[ni][1] = f2tf32(bs[(kk + tg + 4) * BSTR + nb]);
            }
#pragma unroll
            for (int mi = 0; mi < 4; mi++)
#pragma unroll
                for (int ni = 0; ni < 4; ni++) mma_tf32(acc[mi][ni], af[mi], bf[ni]);
        }
        __syncthreads();
    }
#pragma unroll
    for (int mi = 0; mi < 4; mi++) {
#pragma unroll
        for (int r = 0; r < 4; r++) {
            int m = m0 + warp_m * 64 + mi * 16 + g + ((r >> 1) << 3);
            if (m >= M) continue;
#pragma unroll
            for (int ni = 0; ni < 4; ni++) {
                int n = n0 + warp_n * 32 + ni * 8 + tg * 2 + (r & 1);
                float v = acc[mi][ni][r];
                if (bias) v += bias[n];
                v *= alpha;
                size_t off = (size_t)m * N + n;
                if (add) v += add[off];
                C[off] = v;
            }
        }
    }
}

// ---------------- pipelined mma GEMM NT + score epilogue ----------------
// score = sigmoid(A[M,K] @ B[Nn,K]^T); accumulates softplus & pos sums.
// M%128==0, K%16==0, Nn arbitrary.
#define BSTR2 20
__global__ __launch_bounds__(256) void mma_nt_score(const float* __restrict__ A,
                                                    const float* __restrict__ B,
                                                    const int* __restrict__ obj_idx,
                                                    float* __restrict__ out,
                                                    double* __restrict__ accum,
                                                    int M, int Nn, int K) {
    __shared__ float As[2][128 * ASTR];
    __shared__ float Bs[2][128 * BSTR2];
    __shared__ double red[256];
    int tid = threadIdx.x;
    int m0 = blockIdx.y * 128;
    int n0 = blockIdx.x * 128;
    int lane = tid & 31;
    int wid = tid >> 5;
    int warp_m = wid >> 2;
    int warp_n = wid & 3;
    int g = lane >> 2;
    int tg = lane & 3;

    int arow = tid >> 2;
    int ac4 = (tid & 3) << 2;
    const float* asrc0 = A + (size_t)(m0 + arow) * K + ac4;
    const float* asrc1 = A + (size_t)(m0 + arow + 64) * K + ac4;
    int bn0 = min(n0 + arow, Nn - 1);
    int bn1 = min(n0 + arow + 64, Nn - 1);
    const float* bsrc0 = B + (size_t)bn0 * K + ac4;
    const float* bsrc1 = B + (size_t)bn1 * K + ac4;

    uint32_t as_b = (uint32_t)__cvta_generic_to_shared(&As[0][0]);
    uint32_t bs_b = (uint32_t)__cvta_generic_to_shared(&Bs[0][0]);
    uint32_t ad0 = as_b + (arow * ASTR + ac4) * 4;
    uint32_t ad1 = as_b + ((arow + 64) * ASTR + ac4) * 4;
    uint32_t bd0 = bs_b + (arow * BSTR2 + ac4) * 4;
    uint32_t bd1 = bs_b + ((arow + 64) * BSTR2 + ac4) * 4;
    const uint32_t abuf = 128 * ASTR * 4;
    const uint32_t bbuf = 128 * BSTR2 * 4;

    float acc[4][4][4];
#pragma unroll
    for (int i = 0; i < 4; i++)
#pragma unroll
        for (int j = 0; j < 4; j++)
#pragma unroll
            for (int r = 0; r < 4; r++) acc[i][j][r] = 0.0f;

    int KT = K >> 4;
    cp_async16(ad0, asrc0);
    cp_async16(ad1, asrc1);
    cp_async16(bd0, bsrc0);
    cp_async16(bd1, bsrc1);
    cp_commit();

    for (int kt = 0; kt < KT; kt++) {
        int buf = kt & 1;
        if (kt + 1 < KT) {
            int nb = (kt + 1) & 1;
            int koff = (kt + 1) << 4;
            cp_async16(ad0 + nb * abuf, asrc0 + koff);
            cp_async16(ad1 + nb * abuf, asrc1 + koff);
            cp_async16(bd0 + nb * bbuf, bsrc0 + koff);
            cp_async16(bd1 + nb * bbuf, bsrc1 + koff);
        }
        cp_commit();
        cp_wait<1>();
        __syncthreads();
        const float* as = As[buf];
        const float* bs = Bs[buf];
#pragma unroll
        for (int kk = 0; kk < 16; kk += 8) {
            uint32_t af[4][4], bf[4][2];
#pragma unroll
            for (int mi = 0; mi < 4; mi++) {
                int rb = warp_m * 64 + mi * 16 + g;
                af[mi][0] = f2tf32(as[rb * ASTR + kk + tg]);
                af[mi][1] = f2tf32(as[(rb + 8) * ASTR + kk + tg]);
                af[mi][2] = f2tf32(as[rb * ASTR + kk + tg + 4]);
                af[mi][3] = f2tf32(as[(rb + 8) * ASTR + kk + tg + 4]);
            }
#pragma unroll
            for (int ni = 0; ni < 4; ni++) {
                int nb = warp_n * 32 + ni * 8 + g;
                bf[ni][0] = f2tf32(bs[nb * BSTR2 + kk + tg]);
                bf[ni][1] = f2tf32(bs[nb * BSTR2 + kk + tg + 4]);
            }
#pragma unroll
            for (int mi = 0; mi < 4; mi++)
#pragma unroll
                for (int ni = 0; ni < 4; ni++) mma_tf32(acc[mi][ni], af[mi], bf[ni]);
        }
        __syncthreads();
    }

    double sp = 0.0, pos = 0.0;
#pragma unroll
    for (int mi = 0; mi < 4; mi++) {
#pragma unroll
        for (int half = 0; half < 2; half++) {
            int m = m0 + warp_m * 64 + mi * 16 + g + half * 8;
            int obj = obj_idx[m];
#pragma unroll
            for (int ni = 0; ni < 4; ni++) {
                int n = n0 + warp_n * 32 + ni * 8 + tg * 2;
                float s0 = acc[mi][ni][half * 2];
                float s1 = acc[mi][ni][half * 2 + 1];
                float e0 = __expf(-s0), e1 = __expf(-s1);
                float sig0 = 1.0f / (1.0f + e0);
                float sig1 = 1.0f / (1.0f + e1);
                float sp0 = (s0 < -15.0f) ? __expf(s0) : s0 + __logf(1.0f + e0);
                float sp1 = (s1 < -15.0f) ? __expf(s1) : s1 + __logf(1.0f + e1);
                size_t off = (size_t)m * Nn + n;
                if (n + 1 < Nn) {
                    *(float2*)&out[off] = make_float2(sig0, sig1);
                    sp += (double)sp0 + (double)sp1;
                    if (n == obj) pos += (double)s0;
                    if (n + 1 == obj) pos += (double)s1;
                } else if (n < Nn) {
                    out[off] = sig0;
                    sp += (double)sp0;
                    if (n == obj) pos += (double)s0;
                }
            }
        }
    }
    red[tid] = sp;
    __syncthreads();
    for (int o = 128; o > 0; o >>= 1) {
        if (tid < o) red[tid] += red[tid + o];
        __syncthreads();
    }
    if (tid == 0) atomicAdd(&accum[1], red[0]);
    __syncthreads();
    red[tid] = pos;
    __syncthreads();
    for (int o = 128; o > 0; o >>= 1) {
        if (tid < o) red[tid] += red[tid + o];
        __syncthreads();
    }
    if (tid == 0) atomicAdd(&accum[2], red[0]);
}

// ---------------- small helpers ----------------
__global__ void init_kernel(float* H, int n, double* accum) {
    int idx = blockIdx.x * blockDim.x + threadIdx.x;
    if (idx < n) H[idx] = 0.0f;
    if (idx < 3) accum[idx] = 0.0;
}

__global__ void naive_gemm_nt(const float* __restrict__ A, const float* __restrict__ B,
                              float* __restrict__ C, int M, int N, int K) {
    int idx = blockIdx.x * blockDim.x + threadIdx.x;
    if (idx >= M * N) return;
    int m = idx / N, n = idx % N;
    float acc = 0.0f;
    const float* a = A + (size_t)m * K;
    const float* b = B + (size_t)n * K;
    for (int k = 0; k < K; k++) acc += a[k] * b[k];
    C[idx] = acc;
}

__global__ void gru_gates(const float* __restrict__ GI, const float* __restrict__ GH,
                          const float* __restrict__ Hprev, float* __restrict__ Hnew, int M) {
    int idx = blockIdx.x * blockDim.x + threadIdx.x;
    if (idx >= M * HDIM) return;
    int m = idx >> 8;
    int c = idx & 255;
    const float* gi = GI + (size_t)m * 768;
    const float* gh = GH + (size_t)m * 768;
    float r = 1.0f / (1.0f + expf(-(gi[c] + gh[c])));
    float z = 1.0f / (1.0f + expf(-(gi[256 + c] + gh[256 + c])));
    float nn = tanhf(gi[512 + c] + r * gh[512 + c]);
    Hnew[idx] = (1.0f - z) * nn + z * Hprev[idx];
}

__global__ void softmax_p(const float* __restrict__ hist, const float* __restrict__ baseR,
                          const int* __restrict__ rel_idx, float* __restrict__ P) {
    int i = blockIdx.x;
    int t = blockIdx.y;
    int tid = threadIdx.x;
    const float* cur = hist + (size_t)i * (TSTEPS * NREL) + (size_t)t * NREL;
    const float* br = baseR + (size_t)rel_idx[i] * NREL;
    __shared__ float v[NREL];
    __shared__ float red[256];
    float lmax = -3.0e38f;
    for (int j = tid; j < NREL; j += 256) {
        float a = cur[j] * br[j];
        float val = (a == 0.0f) ? -1.0e9f : a;
        v[j] = val;
        lmax = fmaxf(lmax, val);
    }
    red[tid] = lmax;
    __syncthreads();
    for (int o = 128; o > 0; o >>= 1) {
        if (tid < o) red[tid] = fmaxf(red[tid], red[tid + o]);
        __syncthreads();
    }
    float m = red[0];
    __syncthreads();
    float lsum = 0.0f;
    for (int j = tid; j < NREL; j += 256) {
        float e = expf(v[j] - m);
        v[j] = e;
        lsum += e;
    }
    red[tid] = lsum;
    __syncthreads();
    for (int o = 128; o > 0; o >>= 1) {
        if (tid < o) red[tid] += red[tid + o];
        __syncthreads();
    }
    float inv = 1.0f / red[0];
    float* prow = P + ((size_t)t * NTRI + i) * NREL;
    for (int j = tid; j < NREL; j += 256) prow[j] = v[j] * inv;
}

__global__ void u_kernel(const float* __restrict__ prealign, const float* __restrict__ h2rel,
                         const int* __restrict__ sub_idx, const int* __restrict__ rel_idx,
                         float* __restrict__ U) {
    int idx = blockIdx.x * blockDim.x + threadIdx.x;
    if (idx >= NTRI * HDIM) return;
    int m = idx >> 8;
    int c = idx & 255;
    U[idx] = prealign[(size_t)sub_idx[m] * HDIM + c] * h2rel[(size_t)rel_idx[m] * HDIM + c];
}

__global__ void match_reduce(const float* __restrict__ ph_rel, const int* __restrict__ rel_idx,
                             const float* __restrict__ H, double* __restrict__ accum) {
    double local = 0.0;
    for (int idx = blockIdx.x * blockDim.x + threadIdx.x; idx < NTRI * HDIM;
         idx += gridDim.x * blockDim.x) {
        int m = idx >> 8;
        int c = idx & 255;
        float d = ph_rel[(size_t)rel_idx[m] * HDIM + c] - H[idx];
        local += (double)d * (double)d;
    }
    __shared__ double red[256];
    int tid = threadIdx.x;
    red[tid] = local;
    __syncthreads();
    for (int o = 128; o > 0; o >>= 1) {
        if (tid < o) red[tid] += red[tid + o];
        __syncthreads();
    }
    if (tid == 0) atomicAdd(&accum[0], red[0]);
}

__global__ void finalize_kernel(const double* __restrict__ accum, float* __restrict__ out) {
    out[0] = (float)(accum[0] / ((double)NTRI * (double)HDIM));
    out[1] = (float)((accum[1] - accum[2]) / ((double)NTRI * (double)NENT));
}

// ---------------- launch ----------------
extern "C" void kernel_launch(void* const* d_in, const int* in_sizes, int n_in,
                              void* d_out, int out_size) {
    const float* pre_emb = (const float*)d_in[0];
    const float* r_emb = (const float*)d_in[1];
    const float* hist = (const float*)d_in[2];
    const int* sub_idx = (const int*)d_in[3];
    const int* rel_idx = (const int*)d_in[4];
    const int* obj_idx = (const int*)d_in[5];
    int w = (n_in >= 23) ? 7 : 6;
    const float* Wm1 = (const float*)d_in[w + 0];
    const float* bm1 = (const float*)d_in[w + 1];
    const float* Wm2 = (const float*)d_in[w + 2];
    const float* bm2 = (const float*)d_in[w + 3];
    const float* Wattn = (const float*)d_in[w + 4];
    const float* battn = (const float*)d_in[w + 5];
    const float* Wh1 = (const float*)d_in[w + 6];
    const float* bh1 = (const float*)d_in[w + 7];
    const float* Wh2 = (const float*)d_in[w + 8];
    const float* bh2 = (const float*)d_in[w + 9];
    const float* Walign = (const float*)d_in[w + 10];
    const float* balign = (const float*)d_in[w + 11];
    const float* Wih = (const float*)d_in[w + 12];
    const float* Whh = (const float*)d_in[w + 13];
    const float* bih = (const float*)d_in[w + 14];
    const float* bhh = (const float*)d_in[w + 15];

    float *tmp1, *mr, *attW, *baseR, *t1, *ph, *gi2, *gh2, *h2rel;
    float *P, *GI, *GH, *H0, *H1, *prealign, *U;
    double* accum;
    cudaGetSymbolAddress((void**)&tmp1, g_tmp1);
    cudaGetSymbolAddress((void**)&mr, g_mr);
    cudaGetSymbolAddress((void**)&attW, g_attW);
    cudaGetSymbolAddress((void**)&baseR, g_baseR);
    cudaGetSymbolAddress((void**)&t1, g_t1);
    cudaGetSymbolAddress((void**)&ph, g_ph);
    cudaGetSymbolAddress((void**)&gi2, g_gi2);
    cudaGetSymbolAddress((void**)&gh2, g_gh2);
    cudaGetSymbolAddress((void**)&h2rel, g_h2rel);
    cudaGetSymbolAddress((void**)&P, g_P);
    cudaGetSymbolAddress((void**)&GI, g_GI);
    cudaGetSymbolAddress((void**)&GH, g_GH);
    cudaGetSymbolAddress((void**)&H0, g_H0);
    cudaGetSymbolAddress((void**)&H1, g_H1);
    cudaGetSymbolAddress((void**)&prealign, g_prealign);
    cudaGetSymbolAddress((void**)&U, g_U);
    cudaGetSymbolAddress((void**)&accum, g_accum);

    float* out = (float*)d_out;
    float* score = out + 2;

    init_kernel<<<(NTRI * HDIM + 255) / 256, 256>>>(H0, NTRI * HDIM, accum);

    // per-relation precompute
    mma_nn<<<dim3(4, 4), 256>>>(r_emb, Wm1, bm1, nullptr, tmp1, NREL, 512, HDIM, 1.0f);
    mma_nn<<<dim3(2, 4), 256>>>(tmp1, Wm2, bm2, nullptr, mr, NREL, HDIM, 512, 1.0f);
    mma_nn<<<dim3(2, 4), 256>>>(mr, Wattn, battn, nullptr, attW, NREL, HDIM, HDIM, 1.0f);
    naive_gemm_nt<<<(NREL * NREL + 255) / 256, 256>>>(attW, mr, baseR, NREL, NREL, HDIM);
    mma_nn<<<dim3(2, 4), 256>>>(mr, Wh1, bh1, nullptr, t1, NREL, HDIM, HDIM, 1.0f);
    mma_nn<<<dim3(2, 4), 256>>>(t1, Wh2, bh2, mr, ph, NREL, HDIM, HDIM, 0.1f);
    mma_nn<<<dim3(6, 4), 256>>>(mr, Wih, bih, nullptr, gi2, NREL, 768, HDIM, 1.0f);
    mma_nn<<<dim3(6, 4), 256>>>(ph, Whh, bhh, nullptr, gh2, NREL, 768, HDIM, 1.0f);
    gru_gates<<<(NREL * HDIM + 255) / 256, 256>>>(gi2, gh2, ph, h2rel, NREL);

    // attention softmax
    softmax_p<<<dim3(NTRI, TSTEPS), 256>>>(hist, baseR, rel_idx, P);

    // GI = P @ gi2 directly (softmax rows sum to 1 -> bih carried through gi2)
    mma_nn<<<dim3(6, (TSTEPS * NTRI) / 128), 256>>>(P, gi2, nullptr, nullptr, GI,
                                                    TSTEPS * NTRI, 768, NREL, 1.0f);
    // sequential GRU scan
    float* Hc = H0;
    float* Hn = H1;
    for (int t = 0; t < TSTEPS; t++) {
        mma_nn<<<dim3(6, NTRI / 128), 256>>>(Hc, Whh, bhh, nullptr, GH, NTRI, 768, HDIM, 1.0f);
        gru_gates<<<(NTRI * HDIM + 255) / 256, 256>>>(GI + (size_t)t * NTRI * 768, GH, Hc, Hn, NTRI);
        float* tmp = Hc; Hc = Hn; Hn = tmp;
    }

    match_reduce<<<2048, 256>>>(ph, rel_idx, Hc, accum);

    // prealign = pre_emb @ Walign + balign
    mma_nn<<<dim3(2, (NENT + 127) / 128), 256>>>(pre_emb, Walign, balign, nullptr, prealign,
                                                 NENT, HDIM, HDIM, 1.0f);
    u_kernel<<<(NTRI * HDIM + 255) / 256, 256>>>(prealign, h2rel, sub_idx, rel_idx, U);

    // score = sigmoid(U @ prealign^T) + fused loss reductions
    mma_nt_score<<<dim3((NENT + 127) / 128, NTRI / 128), 256>>>(U, prealign, obj_idx, score,
                                                                accum, NTRI, NENT, HDIM);

    finalize_kernel<<<1, 1>>>(accum, out);
}